// round 1
// baseline (speedup 1.0000x reference)
#include <cuda_runtime.h>
#include <math.h>

// Compacted-buffer formulation:
//   layer i: out[c, j] = tanh( sum_k W[i,c,k,0]*in[k,2j] + W[i,c,k,1]*in[k,2j+1] + b[i,c] )
//   => GEMM: A = W[i] viewed as (256 x 512) row-major (exactly its storage layout),
//            B[2k+t, j] = in[k, 2j+t],  C = (256 x Nout)
// N halves each layer: 65536 -> 32768 -> ... -> 1.

#define BM 128
#define BN 128
#define BK 16
#define TM 8
#define TN 8

// ping-pong scratch (even layers write buf0, odd layers write buf1)
__device__ float g_buf0[256 * 32768];   // 32 MB
__device__ float g_buf1[256 * 16384];   // 16 MB

__global__ __launch_bounds__(256) void layer_kernel(
    const float* __restrict__ in,    // 256 x Nin, row-major
    const float* __restrict__ W,     // 256 x 512, row-major (one layer)
    const float* __restrict__ bias,  // 256
    float* __restrict__ out,         // 256 x Nout, row-major
    int Nin, int Nout)
{
    __shared__ float sA[BK][BM + 1];   // transposed A tile: sA[kk][m], pad to dodge bank conflicts
    __shared__ float sB[BK][BN];       // sB[kk][j]

    const int tid = threadIdx.x;          // 0..255
    const int tx  = tid & 15;             // col group
    const int ty  = tid >> 4;             // row group
    const int m0  = blockIdx.y * BM;
    const int j0  = blockIdx.x * BN;

    float acc[TM][TN];
    #pragma unroll
    for (int i = 0; i < TM; i++)
        #pragma unroll
        for (int j = 0; j < TN; j++) acc[i][j] = 0.f;

    for (int k0 = 0; k0 < 512; k0 += BK) {
        // ---- load A tile (128 x 16) transposed into smem ----
        // 2048 floats = 512 float4 loads; 2 per thread
        #pragma unroll
        for (int it = 0; it < 2; it++) {
            int idx = tid + it * 256;        // 0..511
            int row = idx >> 2;              // 0..127
            int kq  = idx & 3;               // 0..3
            float4 v = *reinterpret_cast<const float4*>(
                &W[(m0 + row) * 512 + k0 + kq * 4]);
            sA[kq * 4 + 0][row] = v.x;
            sA[kq * 4 + 1][row] = v.y;
            sA[kq * 4 + 2][row] = v.z;
            sA[kq * 4 + 3][row] = v.w;
        }
        // ---- load B tile (16 x 128) ----
        // B[kk][j] = in[(k0+kk)>>1][2*(j0+j) + (kk&1)]
        // = 8 channels x 256 consecutive time samples (coalesced global reads)
        #pragma unroll
        for (int it = 0; it < 8; it++) {
            int idx = tid + it * 256;        // 0..2047
            int cc  = idx >> 8;              // 0..7 (channel within tile)
            int mm  = idx & 255;             // 0..255 (time offset)
            int ch  = (k0 >> 1) + cc;
            int t   = 2 * j0 + mm;
            float v = (t < Nin) ? in[ch * Nin + t] : 0.f;
            sB[2 * cc + (mm & 1)][mm >> 1] = v;
        }
        __syncthreads();

        // ---- compute ----
        #pragma unroll
        for (int kk = 0; kk < BK; kk++) {
            float a[TM];
            float bb[TN];
            #pragma unroll
            for (int i = 0; i < TM; i++) a[i] = sA[kk][ty * TM + i];
            float4 b0 = *reinterpret_cast<const float4*>(&sB[kk][tx * TN]);
            float4 b1 = *reinterpret_cast<const float4*>(&sB[kk][tx * TN + 4]);
            bb[0] = b0.x; bb[1] = b0.y; bb[2] = b0.z; bb[3] = b0.w;
            bb[4] = b1.x; bb[5] = b1.y; bb[6] = b1.z; bb[7] = b1.w;
            #pragma unroll
            for (int i = 0; i < TM; i++)
                #pragma unroll
                for (int j = 0; j < TN; j++)
                    acc[i][j] += a[i] * bb[j];
        }
        __syncthreads();
    }

    // ---- epilogue: bias + tanh + store ----
    #pragma unroll
    for (int i = 0; i < TM; i++) {
        int m = m0 + ty * TM + i;
        float bv = bias[m];
        #pragma unroll
        for (int j = 0; j < TN; j++) {
            int col = j0 + tx * TN + j;
            if (col < Nout)
                out[m * Nout + col] = tanhf(acc[i][j] + bv);
        }
    }
}

extern "C" void kernel_launch(void* const* d_in, const int* in_sizes, int n_in,
                              void* d_out, int out_size)
{
    const float* x = (const float*)d_in[0];   // (1, 256, 65536)
    const float* W = (const float*)d_in[1];   // (16, 256, 256, 2)
    const float* b = (const float*)d_in[2];   // (16, 256)

    float* buf0 = nullptr;
    float* buf1 = nullptr;
    cudaGetSymbolAddress((void**)&buf0, g_buf0);
    cudaGetSymbolAddress((void**)&buf1, g_buf1);

    int Nin = 65536;
    const float* cur = x;
    for (int i = 0; i < 16; i++) {
        int Nout = Nin >> 1;
        float* outp = (i == 15) ? (float*)d_out : ((i & 1) ? buf1 : buf0);
        dim3 grid((Nout + BN - 1) / BN, 2);
        layer_kernel<<<grid, 256>>>(cur, W + (size_t)i * 256 * 512,
                                    b + i * 256, outp, Nin, Nout);
        cur = outp;
        Nin = Nout;
    }
}